// round 4
// baseline (speedup 1.0000x reference)
#include <cuda_runtime.h>
#include <cuda_bf16.h>
#include <cstdint>

// ---------------------------------------------------------------------------
// MedianConvolution: out[n,c] = lower_median_k( (x @ W^T)[nbrs[n,k], c] )
// N=100000, K=32, IN_C=128, OUT_C=64
// NOTE: reference requests jnp.int64 for nbrs, but JAX demotes to int32
// (x64 disabled) -> device buffer is int32.
// ---------------------------------------------------------------------------

#define N_NODES 100000
#define IN_C    128
#define OUT_C   64
#define KNBR    32

// intermediate h = x @ W^T  (25.6 MB static device scratch — allocation-free)
__device__ float g_h[N_NODES * OUT_C];

// ---------------------------------------------------------------------------
// Kernel 1: h = x @ W^T.  One thread per node row. W kept in smem in its
// native [out=64][in=128] layout (coalesced staging). Compute in 4 chunks of
// 16 output channels; smem reads are float4 with uniform address per warp
// (broadcast, conflict-free).
// ---------------------------------------------------------------------------
__global__ __launch_bounds__(256) void gemm_kernel(
    const float* __restrict__ x,
    const float* __restrict__ W,
    int n)
{
    __shared__ float wsh[OUT_C * IN_C];          // same layout as W: [c][k]

    for (int e = threadIdx.x; e < OUT_C * IN_C; e += 256)
        wsh[e] = W[e];
    __syncthreads();

    const int r = blockIdx.x * 256 + threadIdx.x;
    if (r >= n) return;

    const float4* xr  = reinterpret_cast<const float4*>(x + (size_t)r * IN_C);
    const float4* wr4 = reinterpret_cast<const float4*>(wsh);

#pragma unroll
    for (int cb = 0; cb < 4; cb++) {             // 16 output channels per chunk
        float acc[16];
#pragma unroll
        for (int ci = 0; ci < 16; ci++) acc[ci] = 0.0f;

#pragma unroll 8
        for (int k4 = 0; k4 < IN_C / 4; k4++) {  // 32 float4 along K
            const float4 xv = __ldg(&xr[k4]);    // L1-hit for cb > 0
#pragma unroll
            for (int ci = 0; ci < 16; ci++) {
                const float4 w = wr4[(cb * 16 + ci) * (IN_C / 4) + k4];
                acc[ci] += xv.x * w.x + xv.y * w.y + xv.z * w.z + xv.w * w.w;
            }
        }

        float4* out4 = reinterpret_cast<float4*>(g_h + (size_t)r * OUT_C + cb * 16);
#pragma unroll
        for (int ci = 0; ci < 4; ci++)
            out4[ci] = make_float4(acc[4 * ci], acc[4 * ci + 1],
                                   acc[4 * ci + 2], acc[4 * ci + 3]);
    }
}

// ---------------------------------------------------------------------------
// Kernel 2: gather + lower-median over K=32.
// 256 threads/block = 4 nodes x 64 channels. Warp = 32 consecutive channels
// of one node -> each neighbor gather touches one 128B line (L2-resident).
// Median: bitonic-sort two halves of 16, then take the 16th-smallest of the
// merge via  max_i min(A[i], B[15-i])  (351 min/max ops vs 480 for full sort).
// ---------------------------------------------------------------------------
__device__ __forceinline__ void cas(float& a, float& b) {
    float lo = fminf(a, b);
    float hi = fmaxf(a, b);
    a = lo; b = hi;
}

__device__ __forceinline__ void sort16(float* v) {
#pragma unroll
    for (int k = 2; k <= 16; k <<= 1) {
#pragma unroll
        for (int j = k >> 1; j > 0; j >>= 1) {
#pragma unroll
            for (int i = 0; i < 16; i++) {
                int ixj = i ^ j;
                if (ixj > i) {
                    if ((i & k) == 0) cas(v[i], v[ixj]);
                    else              cas(v[ixj], v[i]);
                }
            }
        }
    }
}

__global__ __launch_bounds__(256) void median_kernel(
    const int* __restrict__ nbrs,      // int32 (JAX demotes int64)
    float* __restrict__ out,
    int n)
{
    __shared__ int snb[4 * KNBR];

    const int base = blockIdx.x * 4;
    const int tid = threadIdx.x;

    if (tid < 4 * KNBR) {
        int node = base + (tid >> 5);
        int idx = (node < n) ? nbrs[(size_t)node * KNBR + (tid & 31)] : 0;
        // defensive clamp: guarantees no OOB even if dtype assumption is wrong
        idx = max(0, min(idx, n - 1));
        snb[tid] = idx;
    }
    __syncthreads();

    const int ty = tid >> 6;   // node within block (0..3)
    const int tx = tid & 63;   // output channel
    const int node = base + ty;
    if (node >= n) return;

    float v[KNBR];
#pragma unroll
    for (int k = 0; k < KNBR; k++) {
        int idx = snb[ty * KNBR + k];           // smem broadcast
        v[k] = __ldg(&g_h[(size_t)idx * OUT_C + tx]);
    }

    sort16(v);
    sort16(v + 16);

    // 16th smallest (rank index 15) of the merge of two sorted 16-arrays
    float med = fminf(v[0], v[31]);
#pragma unroll
    for (int i = 1; i < 16; i++)
        med = fmaxf(med, fminf(v[i], v[31 - i]));

    out[(size_t)node * OUT_C + tx] = med;
}

// ---------------------------------------------------------------------------
extern "C" void kernel_launch(void* const* d_in, const int* in_sizes, int n_in,
                              void* d_out, int out_size) {
    const float* x    = (const float*)d_in[0];
    const int*   nbrs = (const int*)d_in[1];
    const float* W    = (const float*)d_in[2];
    float*       out  = (float*)d_out;

    const int n = in_sizes[0] / IN_C;   // 100000

    gemm_kernel<<<(n + 255) / 256, 256>>>(x, W, n);
    median_kernel<<<(n + 3) / 4, 256>>>(nbrs, out, n);
}